// round 14
// baseline (speedup 1.0000x reference)
#include <cuda_runtime.h>
#include <math.h>

#define BN 2048
#define NN 256
#define MD 1664

typedef unsigned long long ull;

__device__ float g_hi[BN * 128];
__device__ float g_hj[BN * 128];
__device__ float g_m[(size_t)BN * MD];
__device__ float g_part[8][BN][128];
__device__ float g_WgT[256 * 384];     // [k][gatecol]; k<128 = X (Wih), k>=128 = H (Whh)

__device__ __forceinline__ ull ffma2(ull a, ull b, ull c) {
    ull d;
    asm("fma.rn.f32x2 %0, %1, %2, %3;" : "=l"(d) : "l"(a), "l"(b), "l"(c));
    return d;
}
__device__ __forceinline__ ull dup(float a) {
    ull d; asm("mov.b64 %0, {%1,%1};" : "=l"(d) : "f"(a)); return d;
}
__device__ __forceinline__ void unpk(ull v, float& x, float& y) {
    asm("mov.b64 {%0,%1}, %2;" : "=f"(x), "=f"(y) : "l"(v));
}

// ---------------------------------------------------------------------------
// K1: hi/hj projections + input -> g_m[:,0:128] + combined GRU weight transpose
// ---------------------------------------------------------------------------
__global__ void __launch_bounds__(128) k1_hij(const float* __restrict__ input,
                                              const float* __restrict__ preW,
                                              const float* __restrict__ Wih,
                                              const float* __restrict__ Whh) {
    __shared__ float As[8 * 128];
    int t = threadIdx.x;
    int n0 = blockIdx.x * 8;

    for (int idx = blockIdx.x * 128 + t; idx < 384 * 128; idx += 256 * 128) {
        int r = idx >> 7, c = idx & 127;
        g_WgT[c * 384 + r]         = Wih[idx];
        g_WgT[(128 + c) * 384 + r] = Whh[idx];
    }

    for (int s = t; s < 8 * 128; s += 128) {
        float v = input[(size_t)n0 * 128 + s];
        As[s] = v;
        g_m[(size_t)(n0 + (s >> 7)) * MD + (s & 127)] = v;
    }
    __syncthreads();

    float hi[8], hj[8];
#pragma unroll
    for (int r = 0; r < 8; r++) { hi[r] = 0.f; hj[r] = 0.f; }

    for (int e = 0; e < 128; e += 4) {
        float wi0 = preW[(e + 0) * 128 + t];
        float wi1 = preW[(e + 1) * 128 + t];
        float wi2 = preW[(e + 2) * 128 + t];
        float wi3 = preW[(e + 3) * 128 + t];
        float wj0 = preW[(128 + e + 0) * 128 + t];
        float wj1 = preW[(128 + e + 1) * 128 + t];
        float wj2 = preW[(128 + e + 2) * 128 + t];
        float wj3 = preW[(128 + e + 3) * 128 + t];
#pragma unroll
        for (int r = 0; r < 8; r++) {
            const float4 a = *(const float4*)&As[r * 128 + e];
            hi[r] += a.x * wi0 + a.y * wi1 + a.z * wi2 + a.w * wi3;
            hj[r] += a.x * wj0 + a.y * wj1 + a.z * wj2 + a.w * wj3;
        }
    }
#pragma unroll
    for (int r = 0; r < 8; r++) {
        g_hi[(size_t)(n0 + r) * 128 + t] = hi[r];
        g_hj[(size_t)(n0 + r) * 128 + t] = hj[r];
    }
}

// ---------------------------------------------------------------------------
// K2: per-node aggregation (unchanged R13).
// ---------------------------------------------------------------------------
#define EST 36

__global__ void __launch_bounds__(128) k2_agg(const float* __restrict__ adj,
                                              const float* __restrict__ adjf,
                                              const float* __restrict__ preW,
                                              const float* __restrict__ preb) {
    __shared__ float WeS[64 * 128];
    __shared__ float efT[64 * EST];
    __shared__ int   nbr[NN];
    __shared__ int   cnt;

    const int t = threadIdx.x;
    const int node = blockIdx.x;
    const int nbase = (node >> 8) << 8;

    {
        const float4* src = (const float4*)(preW + 256 * 128);
        float4* dst = (float4*)WeS;
#pragma unroll
        for (int i = 0; i < 16; i++) dst[t + i * 128] = src[t + i * 128];
    }
    if (t == 0) cnt = 0;
    __syncthreads();

    const float* arow = adj + (size_t)node * NN;
    for (int j = t; j < NN; j += 128)
        if (arow[j] > 0.0f) { int p = atomicAdd(&cnt, 1); nbr[p] = j; }
    __syncthreads();

    const int deg = cnt;
    const float base = g_hi[(size_t)node * 128 + t] + preb[t];
    float s1 = 0.f, s2 = 0.f, mx = -1e30f, mn = 1e30f;
    const float* efb = adjf + (size_t)node * NN * 64;

    for (int p0 = 0; p0 < deg; p0 += 32) {
        __syncthreads();
        {
            const int e = t & 31, kc = (t >> 5) * 16;
            const int j = (p0 + e < deg) ? nbr[p0 + e] : -1;
            if (j >= 0) {
                const float* src = efb + (size_t)j * 64 + kc;
#pragma unroll
                for (int i = 0; i < 16; i += 4) {
                    float4 v = *(const float4*)(src + i);
                    efT[(kc + i + 0) * EST + e] = v.x;
                    efT[(kc + i + 1) * EST + e] = v.y;
                    efT[(kc + i + 2) * EST + e] = v.z;
                    efT[(kc + i + 3) * EST + e] = v.w;
                }
            } else {
#pragma unroll
                for (int i = 0; i < 16; i++) efT[(kc + i) * EST + e] = 0.f;
            }
        }
        __syncthreads();

        float hjv[32];
#pragma unroll
        for (int u = 0; u < 32; u++) {
            int uu = (p0 + u < deg) ? nbr[p0 + u] : nbr[0];
            hjv[u] = g_hj[(size_t)(nbase + uu) * 128 + t];
        }

        ull acc[16];
#pragma unroll
        for (int p = 0; p < 16; p++) acc[p] = 0;

#pragma unroll 4
        for (int de = 0; de < 64; de++) {
            ull w2 = dup(WeS[de * 128 + t]);
            const ull* efr = (const ull*)&efT[de * EST];
#pragma unroll
            for (int q = 0; q < 8; q++) {
                ulonglong2 e2 = *(const ulonglong2*)&efr[q * 2];
                acc[q * 2]     = ffma2(e2.x, w2, acc[q * 2]);
                acc[q * 2 + 1] = ffma2(e2.y, w2, acc[q * 2 + 1]);
            }
        }

#pragma unroll
        for (int p = 0; p < 16; p++) {
            float ea, eb;
            unpk(acc[p], ea, eb);
            int i0 = p0 + 2 * p, i1 = i0 + 1;
            if (i0 < deg) {
                float tv = base + hjv[2 * p] + ea;
                s1 += tv; s2 += tv * tv;
                mx = fmaxf(mx, tv); mn = fminf(mn, tv);
            }
            if (i1 < deg) {
                float tv = base + hjv[2 * p + 1] + eb;
                s1 += tv; s2 += tv * tv;
                mx = fmaxf(mx, tv); mn = fminf(mn, tv);
            }
        }
    }

    float degf = (float)deg;
    float degc = fmaxf(degf, 1e-5f);
    float mean = s1 / degc;
    float var = s2 / degc - mean * mean;
    if (var < 0.f) var = 0.f;
    float sd = sqrtf(var + 1e-5f);
    float mxo = (deg > 0) ? mx : 0.f;
    float mno = (deg > 0) ? mn : 0.f;
    float slog = logf(degf + 1.0f) / 3.3f;
    float inv = 1.0f / (slog + 1e-5f);

    float* mrow = g_m + (size_t)node * MD;
    mrow[ 128 + t] = mean;        mrow[ 256 + t] = mxo;
    mrow[ 384 + t] = mno;         mrow[ 512 + t] = sd;
    mrow[ 640 + t] = mean * slog; mrow[ 768 + t] = mxo * slog;
    mrow[ 896 + t] = mno * slog;  mrow[1024 + t] = sd * slog;
    mrow[1152 + t] = mean * inv;  mrow[1280 + t] = mxo * inv;
    mrow[1408 + t] = mno * inv;   mrow[1536 + t] = sd * inv;
}

// ---------------------------------------------------------------------------
// K3a: post-GEMM partials (unchanged R13).
// ---------------------------------------------------------------------------
#define KSP 208
#define AST 68
#define SMEM_K3A (KSP * AST * 4)

__global__ void __launch_bounds__(256, 2) k3a_post(const float* __restrict__ postW) {
    extern __shared__ float AsT[];
    const int tid = threadIdx.x;
    const int w = tid >> 5, lane = tid & 31;
    const int rb = blockIdx.x & 31, ks = blockIdx.x >> 5;
    const int n0 = rb * 64, k0 = ks * KSP;

    {
        const int r = tid >> 2;
        const int kt = (tid & 3) * 52;
        const float* src = g_m + (size_t)(n0 + r) * MD + k0 + kt;
#pragma unroll
        for (int i = 0; i < 52; i += 4) {
            float4 v = *(const float4*)(src + i);
            AsT[(kt + i + 0) * AST + r] = v.x;
            AsT[(kt + i + 1) * AST + r] = v.y;
            AsT[(kt + i + 2) * AST + r] = v.z;
            AsT[(kt + i + 3) * AST + r] = v.w;
        }
    }
    __syncthreads();

    const int rg = lane >> 2;
    const int cp = lane & 3;
    const int c0 = w * 16 + cp * 4;
    const int bs = rg * 8;
    const int sel = (rg >= 4) ? 4 : 0;
    const int offA = bs + sel;
    const int offB = bs + 4 - sel;

    const float* wp = postW + (size_t)k0 * 128 + c0;

    ull aA0[4], aA1[4], aB0[4], aB1[4];
#pragma unroll
    for (int c = 0; c < 4; c++) { aA0[c] = 0; aA1[c] = 0; aB0[c] = 0; aB1[c] = 0; }

#define LOADW3(buf, b)                                                      \
    {                                                                       \
        _Pragma("unroll")                                                   \
        for (int j = 0; j < 4; j++)                                         \
            buf[j] = *(const float4*)(wp + (size_t)((b) * 4 + j) * 128);    \
    }
#define COMP3(b, buf)                                                       \
    {                                                                       \
        _Pragma("unroll")                                                   \
        for (int j = 0; j < 4; j++) {                                       \
            const int k = (b) * 4 + j;                                      \
            ulonglong2 A = *(const ulonglong2*)&AsT[k * AST + offA];        \
            ulonglong2 B = *(const ulonglong2*)&AsT[k * AST + offB];        \
            ull w0 = dup(buf[j].x), w1 = dup(buf[j].y);                     \
            ull w2 = dup(buf[j].z), w3 = dup(buf[j].w);                     \
            aA0[0] = ffma2(A.x, w0, aA0[0]); aA0[1] = ffma2(A.x, w1, aA0[1]); \
            aA0[2] = ffma2(A.x, w2, aA0[2]); aA0[3] = ffma2(A.x, w3, aA0[3]); \
            aA1[0] = ffma2(A.y, w0, aA1[0]); aA1[1] = ffma2(A.y, w1, aA1[1]); \
            aA1[2] = ffma2(A.y, w2, aA1[2]); aA1[3] = ffma2(A.y, w3, aA1[3]); \
            aB0[0] = ffma2(B.x, w0, aB0[0]); aB0[1] = ffma2(B.x, w1, aB0[1]); \
            aB0[2] = ffma2(B.x, w2, aB0[2]); aB0[3] = ffma2(B.x, w3, aB0[3]); \
            aB1[0] = ffma2(B.y, w0, aB1[0]); aB1[1] = ffma2(B.y, w1, aB1[1]); \
            aB1[2] = ffma2(B.y, w2, aB1[2]); aB1[3] = ffma2(B.y, w3, aB1[3]); \
        }                                                                   \
    }

    float4 wA[4], wB[4];
    LOADW3(wA, 0);
    for (int b = 0; b < 52; b += 2) {
        LOADW3(wB, b + 1);
        COMP3(b, wA);
        if (b + 2 < 52) LOADW3(wA, b + 2);
        COMP3(b + 1, wB);
    }
#undef LOADW3
#undef COMP3

    {
        const int rA = n0 + offA;
        const int rB = n0 + offB;
        float lo[4], hi[4];
#pragma unroll
        for (int c = 0; c < 4; c++) unpk(aA0[c], lo[c], hi[c]);
        *(float4*)&g_part[ks][rA][c0]     = make_float4(lo[0], lo[1], lo[2], lo[3]);
        *(float4*)&g_part[ks][rA + 1][c0] = make_float4(hi[0], hi[1], hi[2], hi[3]);
#pragma unroll
        for (int c = 0; c < 4; c++) unpk(aA1[c], lo[c], hi[c]);
        *(float4*)&g_part[ks][rA + 2][c0] = make_float4(lo[0], lo[1], lo[2], lo[3]);
        *(float4*)&g_part[ks][rA + 3][c0] = make_float4(hi[0], hi[1], hi[2], hi[3]);
#pragma unroll
        for (int c = 0; c < 4; c++) unpk(aB0[c], lo[c], hi[c]);
        *(float4*)&g_part[ks][rB][c0]     = make_float4(lo[0], lo[1], lo[2], lo[3]);
        *(float4*)&g_part[ks][rB + 1][c0] = make_float4(hi[0], hi[1], hi[2], hi[3]);
#pragma unroll
        for (int c = 0; c < 4; c++) unpk(aB1[c], lo[c], hi[c]);
        *(float4*)&g_part[ks][rB + 2][c0] = make_float4(lo[0], lo[1], lo[2], lo[3]);
        *(float4*)&g_part[ks][rB + 3][c0] = make_float4(hi[0], hi[1], hi[2], hi[3]);
    }
}

// ---------------------------------------------------------------------------
// K456: fully fused tail: reduce partials -> mix+leaky -> 4 gate passes ->
// GRU epilogue -> out. grid 128 (16 rows), 512 threads.
// Layout: warp w -> 8 cols; lane: rp = lane>>2 (row-pair), cp = lane&3 ->
// c0 = w*8 + cp*2. Tiles transposed [c][FST], LDS.64 row-pairs (broadcast).
// ---------------------------------------------------------------------------
#define FST 20

__global__ void __launch_bounds__(512) k456_tail(
        const float* __restrict__ postb,
        const float* __restrict__ mixW, const float* __restrict__ mixb,
        const float* __restrict__ hidden, float* __restrict__ out) {
    __shared__ float YsT[128 * FST];   // y1 transposed [c][r]
    __shared__ float S[256 * FST];     // [k][r]: k<128 = X (mix out), k>=128 = H

    const int tid = threadIdx.x;
    const int n0 = blockIdx.x * 16;

    // ---- Phase A: reduce 8 partials (+postb) -> YsT; hidden -> S[128..] ----
    {
        const int r = tid >> 5;
        const int c4 = (tid & 31) * 4;
        float4 s = *(const float4*)(postb + c4);
#pragma unroll
        for (int p = 0; p < 8; p++) {
            float4 v = *(const float4*)&g_part[p][n0 + r][c4];
            s.x += v.x; s.y += v.y; s.z += v.z; s.w += v.w;
        }
        YsT[(c4 + 0) * FST + r] = s.x;
        YsT[(c4 + 1) * FST + r] = s.y;
        YsT[(c4 + 2) * FST + r] = s.z;
        YsT[(c4 + 3) * FST + r] = s.w;
        float4 h = *(const float4*)(hidden + (size_t)(n0 + r) * 128 + c4);
        S[(128 + c4 + 0) * FST + r] = h.x;
        S[(128 + c4 + 1) * FST + r] = h.y;
        S[(128 + c4 + 2) * FST + r] = h.z;
        S[(128 + c4 + 3) * FST + r] = h.w;
    }
    __syncthreads();

    const int w = tid >> 5, lane = tid & 31;
    const int rp = lane >> 2, cp = lane & 3;
    const int c0 = w * 8 + cp * 2;
    const int r2 = rp * 2;

    // generic double-buffered pass: A (transposed, stride FST) x W -> 2 accs
#define GEMM_PASS(Abase, wptr, wstride, NB, accA, accB)                      \
    {                                                                        \
        ull wbA[4], wbB[4];                                                  \
        _Pragma("unroll")                                                    \
        for (int j = 0; j < 4; j++)                                          \
            wbA[j] = *(const ull*)((wptr) + (size_t)j * (wstride));          \
        for (int b = 0; b < (NB); b += 2) {                                  \
            _Pragma("unroll")                                                \
            for (int j = 0; j < 4; j++)                                      \
                wbB[j] = *(const ull*)((wptr) + (size_t)((b + 1) * 4 + j) * (wstride)); \
            _Pragma("unroll")                                                \
            for (int j = 0; j < 4; j++) {                                    \
                const int k = b * 4 + j;                                     \
                ull av = *(const ull*)&(Abase)[k * FST + r2];                \
                float wlo, whi; unpk(wbA[j], wlo, whi);                      \
                accA = ffma2(av, dup(wlo), accA);                            \
                accB = ffma2(av, dup(whi), accB);                            \
            }                                                                \
            if (b + 2 < (NB)) {                                              \
                _Pragma("unroll")                                            \
                for (int j = 0; j < 4; j++)                                  \
                    wbA[j] = *(const ull*)((wptr) + (size_t)((b + 2) * 4 + j) * (wstride)); \
            }                                                                \
            _Pragma("unroll")                                                \
            for (int j = 0; j < 4; j++) {                                    \
                const int k = (b + 1) * 4 + j;                               \
                ull av = *(const ull*)&(Abase)[k * FST + r2];                \
                float wlo, whi; unpk(wbB[j], wlo, whi);                      \
                accA = ffma2(av, dup(wlo), accA);                            \
                accB = ffma2(av, dup(whi), accB);                            \
            }                                                                \
        }                                                                    \
    }

    // ---- Phase B: X = leaky(Y @ mixW + mixb) -> S[0..127] ----
    {
        ull m0 = 0, m1 = 0;
        const float* wp = mixW + c0;
        GEMM_PASS(YsT, wp, 128, 32, m0, m1);
        float b0 = mixb[c0], b1 = mixb[c0 + 1];
        float x00, x10, x01, x11;
        unpk(m0, x00, x10);   // rows r2, r2+1 at col c0
        unpk(m1, x01, x11);   // at col c0+1
        x00 += b0; x01 += b1; x10 += b0; x11 += b1;
        x00 = (x00 > 0.f) ? x00 : 0.01f * x00;
        x01 = (x01 > 0.f) ? x01 : 0.01f * x01;
        x10 = (x10 > 0.f) ? x10 : 0.01f * x10;
        x11 = (x11 > 0.f) ? x11 : 0.01f * x11;
        *(float2*)&S[(c0 + 0) * FST + r2] = make_float2(x00, x10);
        *(float2*)&S[(c0 + 1) * FST + r2] = make_float2(x01, x11);
    }
    __syncthreads();

    // ---- Phase C: 4 gate passes ----
    ull R0 = 0, R1 = 0, Z0 = 0, Z1 = 0, I0 = 0, I1 = 0, H0 = 0, H1 = 0;
    {   // R: k 0..255, gate cols 0..127
        const float* wp = g_WgT + c0;
        GEMM_PASS(S, wp, 384, 64, R0, R1);
    }
    {   // Z: k 0..255, gate cols 128..255
        const float* wp = g_WgT + 128 + c0;
        GEMM_PASS(S, wp, 384, 64, Z0, Z1);
    }
    {   // I: k 0..127 (X), gate cols 256..383
        const float* wp = g_WgT + 256 + c0;
        GEMM_PASS(S, wp, 384, 32, I0, I1);
    }
    {   // Hn: k 128..255 (H), gate cols 256..383
        const float* wp = g_WgT + (size_t)128 * 384 + 256 + c0;
        const float* Ab = S + 128 * FST;
        GEMM_PASS(Ab, wp, 384, 32, H0, H1);
    }
#undef GEMM_PASS

    // ---- GRU epilogue: rows r2, r2+1 x cols c0, c0+1 ----
    {
        float Ra, Rb, Rc, Rd, Za, Zb, Zc, Zd, Ia, Ib, Ic, Id, Ha, Hb, Hc, Hd;
        unpk(R0, Ra, Rc); unpk(R1, Rb, Rd);   // a=(r2,c0) b=(r2,c1) c=(r2+1,c0) d=(r2+1,c1)
        unpk(Z0, Za, Zc); unpk(Z1, Zb, Zd);
        unpk(I0, Ia, Ic); unpk(I1, Ib, Id);
        unpk(H0, Ha, Hc); unpk(H1, Hb, Hd);
        float hva = S[(128 + c0) * FST + r2];
        float hvc = S[(128 + c0) * FST + r2 + 1];
        float hvb = S[(128 + c0 + 1) * FST + r2];
        float hvd = S[(128 + c0 + 1) * FST + r2 + 1];

        float rv, zv, nv;
        rv = 1.f / (1.f + expf(-Ra)); zv = 1.f / (1.f + expf(-Za));
        nv = tanhf(Ia + rv * Ha);
        float oa = (1.f - zv) * nv + zv * hva;
        rv = 1.f / (1.f + expf(-Rb)); zv = 1.f / (1.f + expf(-Zb));
        nv = tanhf(Ib + rv * Hb);
        float ob = (1.f - zv) * nv + zv * hvb;
        rv = 1.f / (1.f + expf(-Rc)); zv = 1.f / (1.f + expf(-Zc));
        nv = tanhf(Ic + rv * Hc);
        float oc = (1.f - zv) * nv + zv * hvc;
        rv = 1.f / (1.f + expf(-Rd)); zv = 1.f / (1.f + expf(-Zd));
        nv = tanhf(Id + rv * Hd);
        float od = (1.f - zv) * nv + zv * hvd;

        *(float2*)&out[(size_t)(n0 + r2) * 128 + c0]     = make_float2(oa, ob);
        *(float2*)&out[(size_t)(n0 + r2 + 1) * 128 + c0] = make_float2(oc, od);
    }
}

// ---------------------------------------------------------------------------
extern "C" void kernel_launch(void* const* d_in, const int* in_sizes, int n_in,
                              void* d_out, int out_size) {
    const float* input  = (const float*)d_in[0];
    const float* adj    = (const float*)d_in[1];
    const float* adjf   = (const float*)d_in[2];
    const float* hidden = (const float*)d_in[3];
    const float* preW   = (const float*)d_in[4];
    const float* preb   = (const float*)d_in[5];
    const float* postW  = (const float*)d_in[6];
    const float* postb  = (const float*)d_in[7];
    const float* mixW   = (const float*)d_in[8];
    const float* mixb   = (const float*)d_in[9];
    const float* Wih    = (const float*)d_in[10];
    const float* Whh    = (const float*)d_in[11];
    float* out = (float*)d_out;

    cudaFuncSetAttribute(k3a_post, cudaFuncAttributeMaxDynamicSharedMemorySize, SMEM_K3A);

    k1_hij<<<256, 128>>>(input, preW, Wih, Whh);
    k2_agg<<<BN, 128>>>(adj, adjf, preW, preb);
    k3a_post<<<256, 256, SMEM_K3A>>>(postW);
    k456_tail<<<128, 512>>>(postb, mixW, mixb, hidden, out);
}

// round 15
// speedup vs baseline: 1.0049x; 1.0049x over previous
#include <cuda_runtime.h>
#include <math.h>

#define BN 2048
#define NN 256
#define MD 1664

typedef unsigned long long ull;

__device__ float g_hi[BN * 128];
__device__ float g_hj[BN * 128];
__device__ float g_m[(size_t)BN * MD];
__device__ float g_part[8][BN][128];
__device__ float g_WgT[256 * 384];
__device__ float g_gate[(size_t)BN * 384];  // r_sum | z_sum | i_n
__device__ float g_gateH[BN * 128];         // h_n

__device__ __forceinline__ ull ffma2(ull a, ull b, ull c) {
    ull d;
    asm("fma.rn.f32x2 %0, %1, %2, %3;" : "=l"(d) : "l"(a), "l"(b), "l"(c));
    return d;
}
__device__ __forceinline__ ull dup(float a) {
    ull d; asm("mov.b64 %0, {%1,%1};" : "=l"(d) : "f"(a)); return d;
}
__device__ __forceinline__ void unpk(ull v, float& x, float& y) {
    asm("mov.b64 {%0,%1}, %2;" : "=f"(x), "=f"(y) : "l"(v));
}

// ---------------------------------------------------------------------------
// K1: hi/hj projections + input -> g_m[:,0:128] + GRU weight transpose
// ---------------------------------------------------------------------------
__global__ void __launch_bounds__(128) k1_hij(const float* __restrict__ input,
                                              const float* __restrict__ preW,
                                              const float* __restrict__ Wih,
                                              const float* __restrict__ Whh) {
    __shared__ float As[8 * 128];
    int t = threadIdx.x;
    int n0 = blockIdx.x * 8;

    for (int idx = blockIdx.x * 128 + t; idx < 384 * 128; idx += 256 * 128) {
        int r = idx >> 7, c = idx & 127;
        g_WgT[c * 384 + r]         = Wih[idx];
        g_WgT[(128 + c) * 384 + r] = Whh[idx];
    }

    for (int s = t; s < 8 * 128; s += 128) {
        float v = input[(size_t)n0 * 128 + s];
        As[s] = v;
        g_m[(size_t)(n0 + (s >> 7)) * MD + (s & 127)] = v;
    }
    __syncthreads();

    float hi[8], hj[8];
#pragma unroll
    for (int r = 0; r < 8; r++) { hi[r] = 0.f; hj[r] = 0.f; }

    for (int e = 0; e < 128; e += 4) {
        float wi0 = preW[(e + 0) * 128 + t];
        float wi1 = preW[(e + 1) * 128 + t];
        float wi2 = preW[(e + 2) * 128 + t];
        float wi3 = preW[(e + 3) * 128 + t];
        float wj0 = preW[(128 + e + 0) * 128 + t];
        float wj1 = preW[(128 + e + 1) * 128 + t];
        float wj2 = preW[(128 + e + 2) * 128 + t];
        float wj3 = preW[(128 + e + 3) * 128 + t];
#pragma unroll
        for (int r = 0; r < 8; r++) {
            const float4 a = *(const float4*)&As[r * 128 + e];
            hi[r] += a.x * wi0 + a.y * wi1 + a.z * wi2 + a.w * wi3;
            hj[r] += a.x * wj0 + a.y * wj1 + a.z * wj2 + a.w * wj3;
        }
    }
#pragma unroll
    for (int r = 0; r < 8; r++) {
        g_hi[(size_t)(n0 + r) * 128 + t] = hi[r];
        g_hj[(size_t)(n0 + r) * 128 + t] = hj[r];
    }
}

// ---------------------------------------------------------------------------
// K2: per-node aggregation (unchanged).
// ---------------------------------------------------------------------------
#define EST 36

__global__ void __launch_bounds__(128) k2_agg(const float* __restrict__ adj,
                                              const float* __restrict__ adjf,
                                              const float* __restrict__ preW,
                                              const float* __restrict__ preb) {
    __shared__ float WeS[64 * 128];
    __shared__ float efT[64 * EST];
    __shared__ int   nbr[NN];
    __shared__ int   cnt;

    const int t = threadIdx.x;
    const int node = blockIdx.x;
    const int nbase = (node >> 8) << 8;

    {
        const float4* src = (const float4*)(preW + 256 * 128);
        float4* dst = (float4*)WeS;
#pragma unroll
        for (int i = 0; i < 16; i++) dst[t + i * 128] = src[t + i * 128];
    }
    if (t == 0) cnt = 0;
    __syncthreads();

    const float* arow = adj + (size_t)node * NN;
    for (int j = t; j < NN; j += 128)
        if (arow[j] > 0.0f) { int p = atomicAdd(&cnt, 1); nbr[p] = j; }
    __syncthreads();

    const int deg = cnt;
    const float base = g_hi[(size_t)node * 128 + t] + preb[t];
    float s1 = 0.f, s2 = 0.f, mx = -1e30f, mn = 1e30f;
    const float* efb = adjf + (size_t)node * NN * 64;

    for (int p0 = 0; p0 < deg; p0 += 32) {
        __syncthreads();
        {
            const int e = t & 31, kc = (t >> 5) * 16;
            const int j = (p0 + e < deg) ? nbr[p0 + e] : -1;
            if (j >= 0) {
                const float* src = efb + (size_t)j * 64 + kc;
#pragma unroll
                for (int i = 0; i < 16; i += 4) {
                    float4 v = *(const float4*)(src + i);
                    efT[(kc + i + 0) * EST + e] = v.x;
                    efT[(kc + i + 1) * EST + e] = v.y;
                    efT[(kc + i + 2) * EST + e] = v.z;
                    efT[(kc + i + 3) * EST + e] = v.w;
                }
            } else {
#pragma unroll
                for (int i = 0; i < 16; i++) efT[(kc + i) * EST + e] = 0.f;
            }
        }
        __syncthreads();

        float hjv[32];
#pragma unroll
        for (int u = 0; u < 32; u++) {
            int uu = (p0 + u < deg) ? nbr[p0 + u] : nbr[0];
            hjv[u] = g_hj[(size_t)(nbase + uu) * 128 + t];
        }

        ull acc[16];
#pragma unroll
        for (int p = 0; p < 16; p++) acc[p] = 0;

#pragma unroll 4
        for (int de = 0; de < 64; de++) {
            ull w2 = dup(WeS[de * 128 + t]);
            const ull* efr = (const ull*)&efT[de * EST];
#pragma unroll
            for (int q = 0; q < 8; q++) {
                ulonglong2 e2 = *(const ulonglong2*)&efr[q * 2];
                acc[q * 2]     = ffma2(e2.x, w2, acc[q * 2]);
                acc[q * 2 + 1] = ffma2(e2.y, w2, acc[q * 2 + 1]);
            }
        }

#pragma unroll
        for (int p = 0; p < 16; p++) {
            float ea, eb;
            unpk(acc[p], ea, eb);
            int i0 = p0 + 2 * p, i1 = i0 + 1;
            if (i0 < deg) {
                float tv = base + hjv[2 * p] + ea;
                s1 += tv; s2 += tv * tv;
                mx = fmaxf(mx, tv); mn = fminf(mn, tv);
            }
            if (i1 < deg) {
                float tv = base + hjv[2 * p + 1] + eb;
                s1 += tv; s2 += tv * tv;
                mx = fmaxf(mx, tv); mn = fminf(mn, tv);
            }
        }
    }

    float degf = (float)deg;
    float degc = fmaxf(degf, 1e-5f);
    float mean = s1 / degc;
    float var = s2 / degc - mean * mean;
    if (var < 0.f) var = 0.f;
    float sd = sqrtf(var + 1e-5f);
    float mxo = (deg > 0) ? mx : 0.f;
    float mno = (deg > 0) ? mn : 0.f;
    float slog = logf(degf + 1.0f) / 3.3f;
    float inv = 1.0f / (slog + 1e-5f);

    float* mrow = g_m + (size_t)node * MD;
    mrow[ 128 + t] = mean;        mrow[ 256 + t] = mxo;
    mrow[ 384 + t] = mno;         mrow[ 512 + t] = sd;
    mrow[ 640 + t] = mean * slog; mrow[ 768 + t] = mxo * slog;
    mrow[ 896 + t] = mno * slog;  mrow[1024 + t] = sd * slog;
    mrow[1152 + t] = mean * inv;  mrow[1280 + t] = mxo * inv;
    mrow[1408 + t] = mno * inv;   mrow[1536 + t] = sd * inv;
}

// ---------------------------------------------------------------------------
// K3a: post-GEMM partials (unchanged).
// ---------------------------------------------------------------------------
#define KSP 208
#define AST 68
#define SMEM_K3A (KSP * AST * 4)

__global__ void __launch_bounds__(256, 2) k3a_post(const float* __restrict__ postW) {
    extern __shared__ float AsT[];
    const int tid = threadIdx.x;
    const int w = tid >> 5, lane = tid & 31;
    const int rb = blockIdx.x & 31, ks = blockIdx.x >> 5;
    const int n0 = rb * 64, k0 = ks * KSP;

    {
        const int r = tid >> 2;
        const int kt = (tid & 3) * 52;
        const float* src = g_m + (size_t)(n0 + r) * MD + k0 + kt;
#pragma unroll
        for (int i = 0; i < 52; i += 4) {
            float4 v = *(const float4*)(src + i);
            AsT[(kt + i + 0) * AST + r] = v.x;
            AsT[(kt + i + 1) * AST + r] = v.y;
            AsT[(kt + i + 2) * AST + r] = v.z;
            AsT[(kt + i + 3) * AST + r] = v.w;
        }
    }
    __syncthreads();

    const int rg = lane >> 2;
    const int cp = lane & 3;
    const int c0 = w * 16 + cp * 4;
    const int bs = rg * 8;
    const int sel = (rg >= 4) ? 4 : 0;
    const int offA = bs + sel;
    const int offB = bs + 4 - sel;

    const float* wp = postW + (size_t)k0 * 128 + c0;

    ull aA0[4], aA1[4], aB0[4], aB1[4];
#pragma unroll
    for (int c = 0; c < 4; c++) { aA0[c] = 0; aA1[c] = 0; aB0[c] = 0; aB1[c] = 0; }

#define LOADW3(buf, b)                                                      \
    {                                                                       \
        _Pragma("unroll")                                                   \
        for (int j = 0; j < 4; j++)                                         \
            buf[j] = *(const float4*)(wp + (size_t)((b) * 4 + j) * 128);    \
    }
#define COMP3(b, buf)                                                       \
    {                                                                       \
        _Pragma("unroll")                                                   \
        for (int j = 0; j < 4; j++) {                                       \
            const int k = (b) * 4 + j;                                      \
            ulonglong2 A = *(const ulonglong2*)&AsT[k * AST + offA];        \
            ulonglong2 B = *(const ulonglong2*)&AsT[k * AST + offB];        \
            ull w0 = dup(buf[j].x), w1 = dup(buf[j].y);                     \
            ull w2 = dup(buf[j].z), w3 = dup(buf[j].w);                     \
            aA0[0] = ffma2(A.x, w0, aA0[0]); aA0[1] = ffma2(A.x, w1, aA0[1]); \
            aA0[2] = ffma2(A.x, w2, aA0[2]); aA0[3] = ffma2(A.x, w3, aA0[3]); \
            aA1[0] = ffma2(A.y, w0, aA1[0]); aA1[1] = ffma2(A.y, w1, aA1[1]); \
            aA1[2] = ffma2(A.y, w2, aA1[2]); aA1[3] = ffma2(A.y, w3, aA1[3]); \
            aB0[0] = ffma2(B.x, w0, aB0[0]); aB0[1] = ffma2(B.x, w1, aB0[1]); \
            aB0[2] = ffma2(B.x, w2, aB0[2]); aB0[3] = ffma2(B.x, w3, aB0[3]); \
            aB1[0] = ffma2(B.y, w0, aB1[0]); aB1[1] = ffma2(B.y, w1, aB1[1]); \
            aB1[2] = ffma2(B.y, w2, aB1[2]); aB1[3] = ffma2(B.y, w3, aB1[3]); \
        }                                                                   \
    }

    float4 wA[4], wB[4];
    LOADW3(wA, 0);
    for (int b = 0; b < 52; b += 2) {
        LOADW3(wB, b + 1);
        COMP3(b, wA);
        if (b + 2 < 52) LOADW3(wA, b + 2);
        COMP3(b + 1, wB);
    }
#undef LOADW3
#undef COMP3

    {
        const int rA = n0 + offA;
        const int rB = n0 + offB;
        float lo[4], hi[4];
#pragma unroll
        for (int c = 0; c < 4; c++) unpk(aA0[c], lo[c], hi[c]);
        *(float4*)&g_part[ks][rA][c0]     = make_float4(lo[0], lo[1], lo[2], lo[3]);
        *(float4*)&g_part[ks][rA + 1][c0] = make_float4(hi[0], hi[1], hi[2], hi[3]);
#pragma unroll
        for (int c = 0; c < 4; c++) unpk(aA1[c], lo[c], hi[c]);
        *(float4*)&g_part[ks][rA + 2][c0] = make_float4(lo[0], lo[1], lo[2], lo[3]);
        *(float4*)&g_part[ks][rA + 3][c0] = make_float4(hi[0], hi[1], hi[2], hi[3]);
#pragma unroll
        for (int c = 0; c < 4; c++) unpk(aB0[c], lo[c], hi[c]);
        *(float4*)&g_part[ks][rB][c0]     = make_float4(lo[0], lo[1], lo[2], lo[3]);
        *(float4*)&g_part[ks][rB + 1][c0] = make_float4(hi[0], hi[1], hi[2], hi[3]);
#pragma unroll
        for (int c = 0; c < 4; c++) unpk(aB1[c], lo[c], hi[c]);
        *(float4*)&g_part[ks][rB + 2][c0] = make_float4(lo[0], lo[1], lo[2], lo[3]);
        *(float4*)&g_part[ks][rB + 3][c0] = make_float4(hi[0], hi[1], hi[2], hi[3]);
    }
}

// ---------------------------------------------------------------------------
// K45 v2: fused reduce + mix + GRU gate GEMM. grid 192 (64 rowblocks x 3 cb),
// 512 threads (16 warps). Half wg = tid>>8 owns 16 of the 32 rows.
// Lane: rp = lane>>2 row-pair, cp = lane&3 -> c0 = w*16 + cp*4.
// Per k: LDS.64 A-pair + LDG.128 W + 4 dup + 4 FFMA2.
// ---------------------------------------------------------------------------
#define FST 36
#define SMEM_K45 ((128 * FST + 256 * FST) * 4)   // 55296 B

__global__ void __launch_bounds__(512) k45_fused(
        const float* __restrict__ postb,
        const float* __restrict__ mixW, const float* __restrict__ mixb,
        const float* __restrict__ hidden) {
    extern __shared__ float sm[];
    float* YsT = sm;                 // [c][r], c<128
    float* S   = sm + 128 * FST;     // [k][r], k<128 X, k>=128 H

    const int tid = threadIdx.x;
    const int rb = blockIdx.x & 63, cb = blockIdx.x >> 6;
    const int n0 = rb * 32, cg = cb * 128;

    // ---- Phase A: reduce partials -> YsT; hidden -> S[128..255] ----
    {
        const int r = tid >> 4;            // 0..31
        const int c8 = (tid & 15) * 8;
#pragma unroll
        for (int j = 0; j < 2; j++) {
            int c = c8 + j * 4;
            float4 s = *(const float4*)(postb + c);
#pragma unroll
            for (int p = 0; p < 8; p++) {
                float4 v = *(const float4*)&g_part[p][n0 + r][c];
                s.x += v.x; s.y += v.y; s.z += v.z; s.w += v.w;
            }
            YsT[(c + 0) * FST + r] = s.x;
            YsT[(c + 1) * FST + r] = s.y;
            YsT[(c + 2) * FST + r] = s.z;
            YsT[(c + 3) * FST + r] = s.w;
            float4 h = *(const float4*)(hidden + (size_t)(n0 + r) * 128 + c);
            S[(128 + c + 0) * FST + r] = h.x;
            S[(128 + c + 1) * FST + r] = h.y;
            S[(128 + c + 2) * FST + r] = h.z;
            S[(128 + c + 3) * FST + r] = h.w;
        }
    }
    __syncthreads();

    const int w = (tid >> 5) & 7;
    const int wg = tid >> 8;
    const int lane = tid & 31;
    const int rp = lane >> 2, cp = lane & 3;
    const int c0 = w * 16 + cp * 4;
    const int r2 = wg * 16 + rp * 2;

#define GEMM_PASS(Abase, wptr, wstride, NB, a)                               \
    {                                                                        \
        float4 wbA[4], wbB[4];                                               \
        _Pragma("unroll")                                                    \
        for (int j = 0; j < 4; j++)                                          \
            wbA[j] = *(const float4*)((wptr) + (size_t)j * (wstride));       \
        for (int b = 0; b < (NB); b += 2) {                                  \
            _Pragma("unroll")                                                \
            for (int j = 0; j < 4; j++)                                      \
                wbB[j] = *(const float4*)((wptr) + (size_t)((b + 1) * 4 + j) * (wstride)); \
            _Pragma("unroll")                                                \
            for (int j = 0; j < 4; j++) {                                    \
                const int k = b * 4 + j;                                     \
                ull av = *(const ull*)&(Abase)[k * FST + r2];                \
                a[0] = ffma2(av, dup(wbA[j].x), a[0]);                       \
                a[1] = ffma2(av, dup(wbA[j].y), a[1]);                       \
                a[2] = ffma2(av, dup(wbA[j].z), a[2]);                       \
                a[3] = ffma2(av, dup(wbA[j].w), a[3]);                       \
            }                                                                \
            if (b + 2 < (NB)) {                                              \
                _Pragma("unroll")                                            \
                for (int j = 0; j < 4; j++)                                  \
                    wbA[j] = *(const float4*)((wptr) + (size_t)((b + 2) * 4 + j) * (wstride)); \
            }                                                                \
            _Pragma("unroll")                                                \
            for (int j = 0; j < 4; j++) {                                    \
                const int k = (b + 1) * 4 + j;                               \
                ull av = *(const ull*)&(Abase)[k * FST + r2];                \
                a[0] = ffma2(av, dup(wbB[j].x), a[0]);                       \
                a[1] = ffma2(av, dup(wbB[j].y), a[1]);                       \
                a[2] = ffma2(av, dup(wbB[j].z), a[2]);                       \
                a[3] = ffma2(av, dup(wbB[j].w), a[3]);                       \
            }                                                                \
        }                                                                    \
    }

    // ---- Phase B: X = leaky(Y @ mixW + mixb) -> S[0..127] ----
    {
        ull m[4] = {0, 0, 0, 0};
        const float* wp = mixW + c0;
        GEMM_PASS(YsT, wp, 128, 32, m);
#pragma unroll
        for (int c = 0; c < 4; c++) {
            float mb = mixb[c0 + c];
            float x0, x1;
            unpk(m[c], x0, x1);          // rows r2, r2+1
            x0 += mb; x1 += mb;
            x0 = (x0 > 0.f) ? x0 : 0.01f * x0;
            x1 = (x1 > 0.f) ? x1 : 0.01f * x1;
            *(float2*)&S[(c0 + c) * FST + r2] = make_float2(x0, x1);
        }
    }
    __syncthreads();

    // ---- Phase C: gate GEMM ----
    const int nruns = (cb == 2) ? 2 : 1;
    for (int run = 0; run < nruns; run++) {
        ull a[4] = {0, 0, 0, 0};
        const float* wp;
        const float* Ab;
        int NB;
        if (cb < 2)        { wp = g_WgT + cg + c0;                      Ab = S;             NB = 64; }
        else if (run == 0) { wp = g_WgT + 256 + c0;                     Ab = S;             NB = 32; }
        else               { wp = g_WgT + (size_t)128 * 384 + 256 + c0; Ab = S + 128 * FST; NB = 32; }
        GEMM_PASS(Ab, wp, 384, NB, a);

        float* P; int st;
        if (cb < 2)        { P = g_gate + cg + c0;  st = 384; }
        else if (run == 0) { P = g_gate + 256 + c0; st = 384; }
        else               { P = g_gateH + c0;      st = 128; }
        float lo[4], hi[4];
#pragma unroll
        for (int c = 0; c < 4; c++) unpk(a[c], lo[c], hi[c]);
        *(float4*)&P[(size_t)(n0 + r2) * st]     = make_float4(lo[0], lo[1], lo[2], lo[3]);
        *(float4*)&P[(size_t)(n0 + r2 + 1) * st] = make_float4(hi[0], hi[1], hi[2], hi[3]);
    }
#undef GEMM_PASS
}

// ---------------------------------------------------------------------------
// K6: GRU elementwise epilogue -> out.
// ---------------------------------------------------------------------------
__global__ void __launch_bounds__(256) k6_out(const float* __restrict__ hidden,
                                              float* __restrict__ out) {
    int idx = blockIdx.x * 256 + threadIdx.x;
    int r = idx >> 5;
    int c4 = (idx & 31) * 4;
    const float* g = g_gate + (size_t)r * 384;
    float4 rs = *(const float4*)(g + c4);
    float4 zs = *(const float4*)(g + 128 + c4);
    float4 is = *(const float4*)(g + 256 + c4);
    float4 hn = *(const float4*)&g_gateH[(size_t)r * 128 + c4];
    float4 hv = *(const float4*)(hidden + (size_t)r * 128 + c4);
    float o[4];
    float R[4] = {rs.x, rs.y, rs.z, rs.w};
    float Z[4] = {zs.x, zs.y, zs.z, zs.w};
    float I[4] = {is.x, is.y, is.z, is.w};
    float Hn[4] = {hn.x, hn.y, hn.z, hn.w};
    float Hv[4] = {hv.x, hv.y, hv.z, hv.w};
#pragma unroll
    for (int j = 0; j < 4; j++) {
        float rv = 1.f / (1.f + expf(-R[j]));
        float zv = 1.f / (1.f + expf(-Z[j]));
        float nv = tanhf(I[j] + rv * Hn[j]);
        o[j] = (1.f - zv) * nv + zv * Hv[j];
    }
    *(float4*)&out[(size_t)r * 128 + c4] = make_float4(o[0], o[1], o[2], o[3]);
}

// ---------------------------------------------------------------------------
extern "C" void kernel_launch(void* const* d_in, const int* in_sizes, int n_in,
                              void* d_out, int out_size) {
    const float* input  = (const float*)d_in[0];
    const float* adj    = (const float*)d_in[1];
    const float* adjf   = (const float*)d_in[2];
    const float* hidden = (const float*)d_in[3];
    const float* preW   = (const float*)d_in[4];
    const float* preb   = (const float*)d_in[5];
    const float* postW  = (const float*)d_in[6];
    const float* postb  = (const float*)d_in[7];
    const float* mixW   = (const float*)d_in[8];
    const float* mixb   = (const float*)d_in[9];
    const float* Wih    = (const float*)d_in[10];
    const float* Whh    = (const float*)d_in[11];
    float* out = (float*)d_out;

    cudaFuncSetAttribute(k3a_post, cudaFuncAttributeMaxDynamicSharedMemorySize, SMEM_K3A);
    cudaFuncSetAttribute(k45_fused, cudaFuncAttributeMaxDynamicSharedMemorySize, SMEM_K45);

    k1_hij<<<256, 128>>>(input, preW, Wih, Whh);
    k2_agg<<<BN, 128>>>(adj, adjf, preW, preb);
    k3a_post<<<256, 256, SMEM_K3A>>>(postW);
    k45_fused<<<192, 512, SMEM_K45>>>(postb, mixW, mixb, hidden);
    k6_out<<<256, 256>>>(hidden, out);
}

// round 16
// speedup vs baseline: 1.0162x; 1.0113x over previous
#include <cuda_runtime.h>
#include <math.h>

#define BN 2048
#define NN 256
#define MD 1664

typedef unsigned long long ull;

__device__ float g_hi[BN * 128];
__device__ float g_hj[BN * 128];
__device__ float g_m[(size_t)BN * MD];
__device__ float g_part[8][BN][128];
__device__ float g_WgT[256 * 384];          // [k][gatecol]; k<128 = X (Wih), k>=128 = H (Whh)
__device__ float g_gate[(size_t)BN * 384];  // R(k-lo) | Z(k-lo) | i_n
__device__ float g_gate2[(size_t)BN * 256]; // R(k-hi) | Z(k-hi)
__device__ float g_gateH[BN * 128];         // h_n

__device__ __forceinline__ ull ffma2(ull a, ull b, ull c) {
    ull d;
    asm("fma.rn.f32x2 %0, %1, %2, %3;" : "=l"(d) : "l"(a), "l"(b), "l"(c));
    return d;
}
__device__ __forceinline__ ull dup(float a) {
    ull d; asm("mov.b64 %0, {%1,%1};" : "=l"(d) : "f"(a)); return d;
}
__device__ __forceinline__ void unpk(ull v, float& x, float& y) {
    asm("mov.b64 {%0,%1}, %2;" : "=f"(x), "=f"(y) : "l"(v));
}

// ---------------------------------------------------------------------------
// K1: hi/hj projections + input -> g_m[:,0:128] + combined GRU weight transpose
// ---------------------------------------------------------------------------
__global__ void __launch_bounds__(128) k1_hij(const float* __restrict__ input,
                                              const float* __restrict__ preW,
                                              const float* __restrict__ Wih,
                                              const float* __restrict__ Whh) {
    __shared__ float As[8 * 128];
    int t = threadIdx.x;
    int n0 = blockIdx.x * 8;

    for (int idx = blockIdx.x * 128 + t; idx < 384 * 128; idx += 256 * 128) {
        int r = idx >> 7, c = idx & 127;
        g_WgT[c * 384 + r]         = Wih[idx];
        g_WgT[(128 + c) * 384 + r] = Whh[idx];
    }

    for (int s = t; s < 8 * 128; s += 128) {
        float v = input[(size_t)n0 * 128 + s];
        As[s] = v;
        g_m[(size_t)(n0 + (s >> 7)) * MD + (s & 127)] = v;
    }
    __syncthreads();

    float hi[8], hj[8];
#pragma unroll
    for (int r = 0; r < 8; r++) { hi[r] = 0.f; hj[r] = 0.f; }

    for (int e = 0; e < 128; e += 4) {
        float wi0 = preW[(e + 0) * 128 + t];
        float wi1 = preW[(e + 1) * 128 + t];
        float wi2 = preW[(e + 2) * 128 + t];
        float wi3 = preW[(e + 3) * 128 + t];
        float wj0 = preW[(128 + e + 0) * 128 + t];
        float wj1 = preW[(128 + e + 1) * 128 + t];
        float wj2 = preW[(128 + e + 2) * 128 + t];
        float wj3 = preW[(128 + e + 3) * 128 + t];
#pragma unroll
        for (int r = 0; r < 8; r++) {
            const float4 a = *(const float4*)&As[r * 128 + e];
            hi[r] += a.x * wi0 + a.y * wi1 + a.z * wi2 + a.w * wi3;
            hj[r] += a.x * wj0 + a.y * wj1 + a.z * wj2 + a.w * wj3;
        }
    }
#pragma unroll
    for (int r = 0; r < 8; r++) {
        g_hi[(size_t)(n0 + r) * 128 + t] = hi[r];
        g_hj[(size_t)(n0 + r) * 128 + t] = hj[r];
    }
}

// ---------------------------------------------------------------------------
// K2: per-node aggregation (unchanged R13).
// ---------------------------------------------------------------------------
#define EST 36

__global__ void __launch_bounds__(128) k2_agg(const float* __restrict__ adj,
                                              const float* __restrict__ adjf,
                                              const float* __restrict__ preW,
                                              const float* __restrict__ preb) {
    __shared__ float WeS[64 * 128];
    __shared__ float efT[64 * EST];
    __shared__ int   nbr[NN];
    __shared__ int   cnt;

    const int t = threadIdx.x;
    const int node = blockIdx.x;
    const int nbase = (node >> 8) << 8;

    {
        const float4* src = (const float4*)(preW + 256 * 128);
        float4* dst = (float4*)WeS;
#pragma unroll
        for (int i = 0; i < 16; i++) dst[t + i * 128] = src[t + i * 128];
    }
    if (t == 0) cnt = 0;
    __syncthreads();

    const float* arow = adj + (size_t)node * NN;
    for (int j = t; j < NN; j += 128)
        if (arow[j] > 0.0f) { int p = atomicAdd(&cnt, 1); nbr[p] = j; }
    __syncthreads();

    const int deg = cnt;
    const float base = g_hi[(size_t)node * 128 + t] + preb[t];
    float s1 = 0.f, s2 = 0.f, mx = -1e30f, mn = 1e30f;
    const float* efb = adjf + (size_t)node * NN * 64;

    for (int p0 = 0; p0 < deg; p0 += 32) {
        __syncthreads();
        {
            const int e = t & 31, kc = (t >> 5) * 16;
            const int j = (p0 + e < deg) ? nbr[p0 + e] : -1;
            if (j >= 0) {
                const float* src = efb + (size_t)j * 64 + kc;
#pragma unroll
                for (int i = 0; i < 16; i += 4) {
                    float4 v = *(const float4*)(src + i);
                    efT[(kc + i + 0) * EST + e] = v.x;
                    efT[(kc + i + 1) * EST + e] = v.y;
                    efT[(kc + i + 2) * EST + e] = v.z;
                    efT[(kc + i + 3) * EST + e] = v.w;
                }
            } else {
#pragma unroll
                for (int i = 0; i < 16; i++) efT[(kc + i) * EST + e] = 0.f;
            }
        }
        __syncthreads();

        float hjv[32];
#pragma unroll
        for (int u = 0; u < 32; u++) {
            int uu = (p0 + u < deg) ? nbr[p0 + u] : nbr[0];
            hjv[u] = g_hj[(size_t)(nbase + uu) * 128 + t];
        }

        ull acc[16];
#pragma unroll
        for (int p = 0; p < 16; p++) acc[p] = 0;

#pragma unroll 4
        for (int de = 0; de < 64; de++) {
            ull w2 = dup(WeS[de * 128 + t]);
            const ull* efr = (const ull*)&efT[de * EST];
#pragma unroll
            for (int q = 0; q < 8; q++) {
                ulonglong2 e2 = *(const ulonglong2*)&efr[q * 2];
                acc[q * 2]     = ffma2(e2.x, w2, acc[q * 2]);
                acc[q * 2 + 1] = ffma2(e2.y, w2, acc[q * 2 + 1]);
            }
        }

#pragma unroll
        for (int p = 0; p < 16; p++) {
            float ea, eb;
            unpk(acc[p], ea, eb);
            int i0 = p0 + 2 * p, i1 = i0 + 1;
            if (i0 < deg) {
                float tv = base + hjv[2 * p] + ea;
                s1 += tv; s2 += tv * tv;
                mx = fmaxf(mx, tv); mn = fminf(mn, tv);
            }
            if (i1 < deg) {
                float tv = base + hjv[2 * p + 1] + eb;
                s1 += tv; s2 += tv * tv;
                mx = fmaxf(mx, tv); mn = fminf(mn, tv);
            }
        }
    }

    float degf = (float)deg;
    float degc = fmaxf(degf, 1e-5f);
    float mean = s1 / degc;
    float var = s2 / degc - mean * mean;
    if (var < 0.f) var = 0.f;
    float sd = sqrtf(var + 1e-5f);
    float mxo = (deg > 0) ? mx : 0.f;
    float mno = (deg > 0) ? mn : 0.f;
    float slog = logf(degf + 1.0f) / 3.3f;
    float inv = 1.0f / (slog + 1e-5f);

    float* mrow = g_m + (size_t)node * MD;
    mrow[ 128 + t] = mean;        mrow[ 256 + t] = mxo;
    mrow[ 384 + t] = mno;         mrow[ 512 + t] = sd;
    mrow[ 640 + t] = mean * slog; mrow[ 768 + t] = mxo * slog;
    mrow[ 896 + t] = mno * slog;  mrow[1024 + t] = sd * slog;
    mrow[1152 + t] = mean * inv;  mrow[1280 + t] = mxo * inv;
    mrow[1408 + t] = mno * inv;   mrow[1536 + t] = sd * inv;
}

// ---------------------------------------------------------------------------
// K3a: post-GEMM partials (unchanged R13).
// ---------------------------------------------------------------------------
#define KSP 208
#define AST 68
#define SMEM_K3A (KSP * AST * 4)

__global__ void __launch_bounds__(256, 2) k3a_post(const float* __restrict__ postW) {
    extern __shared__ float AsT[];
    const int tid = threadIdx.x;
    const int w = tid >> 5, lane = tid & 31;
    const int rb = blockIdx.x & 31, ks = blockIdx.x >> 5;
    const int n0 = rb * 64, k0 = ks * KSP;

    {
        const int r = tid >> 2;
        const int kt = (tid & 3) * 52;
        const float* src = g_m + (size_t)(n0 + r) * MD + k0 + kt;
#pragma unroll
        for (int i = 0; i < 52; i += 4) {
            float4 v = *(const float4*)(src + i);
            AsT[(kt + i + 0) * AST + r] = v.x;
            AsT[(kt + i + 1) * AST + r] = v.y;
            AsT[(kt + i + 2) * AST + r] = v.z;
            AsT[(kt + i + 3) * AST + r] = v.w;
        }
    }
    __syncthreads();

    const int rg = lane >> 2;
    const int cp = lane & 3;
    const int c0 = w * 16 + cp * 4;
    const int bs = rg * 8;
    const int sel = (rg >= 4) ? 4 : 0;
    const int offA = bs + sel;
    const int offB = bs + 4 - sel;

    const float* wp = postW + (size_t)k0 * 128 + c0;

    ull aA0[4], aA1[4], aB0[4], aB1[4];
#pragma unroll
    for (int c = 0; c < 4; c++) { aA0[c] = 0; aA1[c] = 0; aB0[c] = 0; aB1[c] = 0; }

#define LOADW3(buf, b)                                                      \
    {                                                                       \
        _Pragma("unroll")                                                   \
        for (int j = 0; j < 4; j++)                                         \
            buf[j] = *(const float4*)(wp + (size_t)((b) * 4 + j) * 128);    \
    }
#define COMP3(b, buf)                                                       \
    {                                                                       \
        _Pragma("unroll")                                                   \
        for (int j = 0; j < 4; j++) {                                       \
            const int k = (b) * 4 + j;                                      \
            ulonglong2 A = *(const ulonglong2*)&AsT[k * AST + offA];        \
            ulonglong2 B = *(const ulonglong2*)&AsT[k * AST + offB];        \
            ull w0 = dup(buf[j].x), w1 = dup(buf[j].y);                     \
            ull w2 = dup(buf[j].z), w3 = dup(buf[j].w);                     \
            aA0[0] = ffma2(A.x, w0, aA0[0]); aA0[1] = ffma2(A.x, w1, aA0[1]); \
            aA0[2] = ffma2(A.x, w2, aA0[2]); aA0[3] = ffma2(A.x, w3, aA0[3]); \
            aA1[0] = ffma2(A.y, w0, aA1[0]); aA1[1] = ffma2(A.y, w1, aA1[1]); \
            aA1[2] = ffma2(A.y, w2, aA1[2]); aA1[3] = ffma2(A.y, w3, aA1[3]); \
            aB0[0] = ffma2(B.x, w0, aB0[0]); aB0[1] = ffma2(B.x, w1, aB0[1]); \
            aB0[2] = ffma2(B.x, w2, aB0[2]); aB0[3] = ffma2(B.x, w3, aB0[3]); \
            aB1[0] = ffma2(B.y, w0, aB1[0]); aB1[1] = ffma2(B.y, w1, aB1[1]); \
            aB1[2] = ffma2(B.y, w2, aB1[2]); aB1[3] = ffma2(B.y, w3, aB1[3]); \
        }                                                                   \
    }

    float4 wA[4], wB[4];
    LOADW3(wA, 0);
    for (int b = 0; b < 52; b += 2) {
        LOADW3(wB, b + 1);
        COMP3(b, wA);
        if (b + 2 < 52) LOADW3(wA, b + 2);
        COMP3(b + 1, wB);
    }
#undef LOADW3
#undef COMP3

    {
        const int rA = n0 + offA;
        const int rB = n0 + offB;
        float lo[4], hi[4];
#pragma unroll
        for (int c = 0; c < 4; c++) unpk(aA0[c], lo[c], hi[c]);
        *(float4*)&g_part[ks][rA][c0]     = make_float4(lo[0], lo[1], lo[2], lo[3]);
        *(float4*)&g_part[ks][rA + 1][c0] = make_float4(hi[0], hi[1], hi[2], hi[3]);
#pragma unroll
        for (int c = 0; c < 4; c++) unpk(aA1[c], lo[c], hi[c]);
        *(float4*)&g_part[ks][rA + 2][c0] = make_float4(lo[0], lo[1], lo[2], lo[3]);
        *(float4*)&g_part[ks][rA + 3][c0] = make_float4(hi[0], hi[1], hi[2], hi[3]);
#pragma unroll
        for (int c = 0; c < 4; c++) unpk(aB0[c], lo[c], hi[c]);
        *(float4*)&g_part[ks][rB][c0]     = make_float4(lo[0], lo[1], lo[2], lo[3]);
        *(float4*)&g_part[ks][rB + 1][c0] = make_float4(hi[0], hi[1], hi[2], hi[3]);
#pragma unroll
        for (int c = 0; c < 4; c++) unpk(aB1[c], lo[c], hi[c]);
        *(float4*)&g_part[ks][rB + 2][c0] = make_float4(lo[0], lo[1], lo[2], lo[3]);
        *(float4*)&g_part[ks][rB + 3][c0] = make_float4(hi[0], hi[1], hi[2], hi[3]);
    }
}

// ---------------------------------------------------------------------------
// K45 v3: fused reduce + mix + gate GEMM, R13 microkernel, k-split phase C.
// grid 320 = 64 rowblocks(32 rows) x 5 variants. 256 threads.
// cb0: R k-lo -> g_gate[0:128]    cb1: R k-hi -> g_gate2[0:128]
// cb2: Z k-lo -> g_gate[128:256]  cb3: Z k-hi -> g_gate2[128:256]
// cb4: I (k-lo) -> g_gate[256:384]; Hn (k-hi) -> g_gateH
// ---------------------------------------------------------------------------
#define FST 36
#define SMEM_K45 ((128 * FST + 256 * FST) * 4)   // 55296 B

__global__ void __launch_bounds__(256, 2) k45_fused(
        const float* __restrict__ postb,
        const float* __restrict__ mixW, const float* __restrict__ mixb,
        const float* __restrict__ hidden) {
    extern __shared__ float sm[];
    float* YsT = sm;                 // [c][r], c<128
    float* S   = sm + 128 * FST;     // [k][r], k<128 X, k>=128 H

    const int tid = threadIdx.x;
    const int rb = blockIdx.x & 63, cb = blockIdx.x >> 6;
    const int n0 = rb * 32;

    // ---- Phase A: reduce partials -> YsT; hidden -> S[128..255] ----
    {
        const int r = tid >> 3;
        const int c16 = (tid & 7) * 16;
#pragma unroll
        for (int j = 0; j < 4; j++) {
            int c = c16 + j * 4;
            float4 s = *(const float4*)(postb + c);
#pragma unroll
            for (int p = 0; p < 8; p++) {
                float4 v = *(const float4*)&g_part[p][n0 + r][c];
                s.x += v.x; s.y += v.y; s.z += v.z; s.w += v.w;
            }
            YsT[(c + 0) * FST + r] = s.x;
            YsT[(c + 1) * FST + r] = s.y;
            YsT[(c + 2) * FST + r] = s.z;
            YsT[(c + 3) * FST + r] = s.w;
            float4 h = *(const float4*)(hidden + (size_t)(n0 + r) * 128 + c);
            S[(128 + c + 0) * FST + r] = h.x;
            S[(128 + c + 1) * FST + r] = h.y;
            S[(128 + c + 2) * FST + r] = h.z;
            S[(128 + c + 3) * FST + r] = h.w;
        }
    }
    __syncthreads();

    const int w = tid >> 5, lane = tid & 31;
    const int rq = lane >> 2, cp = lane & 3;
    const int c0 = w * 16 + cp * 4;

#define LOADW45(wp, stride, buf, b)                                          \
    {                                                                        \
        _Pragma("unroll")                                                    \
        for (int j = 0; j < 4; j++)                                          \
            buf[j] = *(const float4*)((wp) + (size_t)((b) * 4 + j) * (stride)); \
    }
#define COMP45(base, b, buf)                                                 \
    {                                                                        \
        _Pragma("unroll")                                                    \
        for (int j = 0; j < 4; j++) {                                        \
            const int k = (b) * 4 + j;                                       \
            ulonglong2 A = *(const ulonglong2*)&(base)[k * FST + rq * 4];    \
            ull w0 = dup(buf[j].x), w1 = dup(buf[j].y);                      \
            ull w2 = dup(buf[j].z), w3 = dup(buf[j].w);                      \
            a0[0] = ffma2(A.x, w0, a0[0]); a0[1] = ffma2(A.x, w1, a0[1]);    \
            a0[2] = ffma2(A.x, w2, a0[2]); a0[3] = ffma2(A.x, w3, a0[3]);    \
            a1[0] = ffma2(A.y, w0, a1[0]); a1[1] = ffma2(A.y, w1, a1[1]);    \
            a1[2] = ffma2(A.y, w2, a1[2]); a1[3] = ffma2(A.y, w3, a1[3]);    \
        }                                                                    \
    }

    // ---- Phase B: X = leaky(Y @ mixW + mixb) -> S[0..127] ----
    {
        const float* wp = mixW + c0;
        ull a0[4] = {0, 0, 0, 0}, a1[4] = {0, 0, 0, 0};
        float4 wA[4], wB[4];
        LOADW45(wp, 128, wA, 0);
        for (int b = 0; b < 32; b += 2) {
            LOADW45(wp, 128, wB, b + 1);
            COMP45(YsT, b, wA);
            if (b + 2 < 32) LOADW45(wp, 128, wA, b + 2);
            COMP45(YsT, b + 1, wB);
        }
#pragma unroll
        for (int c = 0; c < 4; c++) {
            float mb = mixb[c0 + c];
            float x0, x1, x2, x3;
            unpk(a0[c], x0, x1);
            unpk(a1[c], x2, x3);
            x0 += mb; x1 += mb; x2 += mb; x3 += mb;
            x0 = (x0 > 0.f) ? x0 : 0.01f * x0;
            x1 = (x1 > 0.f) ? x1 : 0.01f * x1;
            x2 = (x2 > 0.f) ? x2 : 0.01f * x2;
            x3 = (x3 > 0.f) ? x3 : 0.01f * x3;
            *(float4*)&S[(c0 + c) * FST + rq * 4] = make_float4(x0, x1, x2, x3);
        }
    }
    __syncthreads();

    // ---- Phase C: gate GEMM, one 32-block k-range per variant ----
    const int nruns = (cb == 4) ? 2 : 1;
    for (int run = 0; run < nruns; run++) {
        const float* wp;
        const float* Ab;
        float* P; int st;
        if (cb == 0)       { wp = g_WgT + c0;                              Ab = S;             P = g_gate + c0;        st = 384; }
        else if (cb == 1)  { wp = g_WgT + (size_t)128 * 384 + c0;          Ab = S + 128 * FST; P = g_gate2 + c0;       st = 256; }
        else if (cb == 2)  { wp = g_WgT + 128 + c0;                        Ab = S;             P = g_gate + 128 + c0;  st = 384; }
        else if (cb == 3)  { wp = g_WgT + (size_t)128 * 384 + 128 + c0;    Ab = S + 128 * FST; P = g_gate2 + 128 + c0; st = 256; }
        else if (run == 0) { wp = g_WgT + 256 + c0;                        Ab = S;             P = g_gate + 256 + c0;  st = 384; }
        else               { wp = g_WgT + (size_t)128 * 384 + 256 + c0;    Ab = S + 128 * FST; P = g_gateH + c0;       st = 128; }

        ull a0[4] = {0, 0, 0, 0}, a1[4] = {0, 0, 0, 0};
        float4 wA[4], wB[4];
        LOADW45(wp, 384, wA, 0);
        for (int b = 0; b < 32; b += 2) {
            LOADW45(wp, 384, wB, b + 1);
            COMP45(Ab, b, wA);
            if (b + 2 < 32) LOADW45(wp, 384, wA, b + 2);
            COMP45(Ab, b + 1, wB);
        }

        const int r0 = n0 + rq * 4;
        float lo[4], hi[4];
#pragma unroll
        for (int c = 0; c < 4; c++) unpk(a0[c], lo[c], hi[c]);
        *(float4*)&P[(size_t)(r0 + 0) * st] = make_float4(lo[0], lo[1], lo[2], lo[3]);
        *(float4*)&P[(size_t)(r0 + 1) * st] = make_float4(hi[0], hi[1], hi[2], hi[3]);
#pragma unroll
        for (int c = 0; c < 4; c++) unpk(a1[c], lo[c], hi[c]);
        *(float4*)&P[(size_t)(r0 + 2) * st] = make_float4(lo[0], lo[1], lo[2], lo[3]);
        *(float4*)&P[(size_t)(r0 + 3) * st] = make_float4(hi[0], hi[1], hi[2], hi[3]);
    }
#undef LOADW45
#undef COMP45
}

// ---------------------------------------------------------------------------
// K6: GRU elementwise epilogue -> out (sums the k-split gate halves).
// ---------------------------------------------------------------------------
__global__ void __launch_bounds__(256) k6_out(const float* __restrict__ hidden,
                                              float* __restrict__ out) {
    int idx = blockIdx.x * 256 + threadIdx.x;
    int r = idx >> 5;
    int c4 = (idx & 31) * 4;
    const float* g  = g_gate + (size_t)r * 384;
    const float* g2 = g_gate2 + (size_t)r * 256;
    float4 rsA = *(const float4*)(g + c4);
    float4 rsB = *(const float4*)(g2 + c4);
    float4 zsA = *(const float4*)(g + 128 + c4);
    float4 zsB = *(const float4*)(g2 + 128 + c4);
    float4 is = *(const float4*)(g + 256 + c4);
    float4 hn = *(const float4*)&g_gateH[(size_t)r * 128 + c4];
    float4 hv = *(const float4*)(hidden + (size_t)r * 128 + c4);
    float R[4] = {rsA.x + rsB.x, rsA.y + rsB.y, rsA.z + rsB.z, rsA.w + rsB.w};
    float Z[4] = {zsA.x + zsB.x, zsA.y + zsB.y, zsA.z + zsB.z, zsA.w + zsB.w};
    float I[4] = {is.x, is.y, is.z, is.w};
    float Hn[4] = {hn.x, hn.y, hn.z, hn.w};
    float Hv[4] = {hv.x, hv.y, hv.z, hv.w};
    float o[4];
#pragma unroll
    for (int j = 0; j < 4; j++) {
        float rv = 1.f / (1.f + expf(-R[j]));
        float zv = 1.f / (1.f + expf(-Z[j]));
        float nv = tanhf(I[j] + rv * Hn[j]);
        o[j] = (1.f - zv) * nv + zv * Hv[j];
    }
    *(float4*)&out[(size_t)r * 128 + c4] = make_float4(o[0], o[1], o[2], o[3]);
}

// ---------------------------------------------------------------------------
extern "C" void kernel_launch(void* const* d_in, const int* in_sizes, int n_in,
                              void* d_out, int out_size) {
    const float* input  = (const float*)d_in[0];
    const float* adj    = (const float*)d_in[1];
    const float* adjf   = (const float*)d_in[2];
    const float* hidden = (const float*)d_in[3];
    const float* preW   = (const float*)d_in[4];
    const float* preb   = (const float*)d_in[5];
    const float* postW  = (const float*)d_in[6];
    const float* postb  = (const float*)d_in[7];
    const float* mixW   = (const float*)d_in[8];
    const float* mixb   = (const float*)d_in[9];
    const float* Wih    = (const float*)d_in[10];
    const float* Whh    = (const float*)d_in[11];
    float* out = (float*)d_out;

    cudaFuncSetAttribute(k3a_post, cudaFuncAttributeMaxDynamicSharedMemorySize, SMEM_K3A);
    cudaFuncSetAttribute(k45_fused, cudaFuncAttributeMaxDynamicSharedMemorySize, SMEM_K45);

    k1_hij<<<256, 128>>>(input, preW, Wih, Whh);
    k2_agg<<<BN, 128>>>(adj, adjf, preW, preb);
    k3a_post<<<256, 256, SMEM_K3A>>>(postW);
    k45_fused<<<320, 256, SMEM_K45>>>(postb, mixW, mixb, hidden);
    k6_out<<<256, 256>>>(hidden, out);
}

// round 17
// speedup vs baseline: 1.1493x; 1.1309x over previous
#include <cuda_runtime.h>
#include <math.h>

#define BN 2048
#define NN 256
#define MD 1664

typedef unsigned long long ull;

__device__ float g_hi[BN * 128];
__device__ float g_hj[BN * 128];
__device__ float g_m[(size_t)BN * MD];
__device__ float g_part[8][BN][128];
__device__ float g_WgT[256 * 384];     // [k][gatecol]; k<128 = X (Wih), k>=128 = H (Whh)
__device__ float g_gate[(size_t)BN * 384];  // r_sum | z_sum | i_n
__device__ float g_gateH[BN * 128];    // h_n

__device__ __forceinline__ ull ffma2(ull a, ull b, ull c) {
    ull d;
    asm("fma.rn.f32x2 %0, %1, %2, %3;" : "=l"(d) : "l"(a), "l"(b), "l"(c));
    return d;
}
__device__ __forceinline__ ull dup(float a) {
    ull d; asm("mov.b64 %0, {%1,%1};" : "=l"(d) : "f"(a)); return d;
}
__device__ __forceinline__ void unpk(ull v, float& x, float& y) {
    asm("mov.b64 {%0,%1}, %2;" : "=f"(x), "=f"(y) : "l"(v));
}

// ---------------------------------------------------------------------------
// K1: hi/hj projections + input -> g_m[:,0:128] + combined GRU weight transpose
// ---------------------------------------------------------------------------
__global__ void __launch_bounds__(128) k1_hij(const float* __restrict__ input,
                                              const float* __restrict__ preW,
                                              const float* __restrict__ Wih,
                                              const float* __restrict__ Whh) {
    __shared__ float As[8 * 128];
    int t = threadIdx.x;
    int n0 = blockIdx.x * 8;

    for (int idx = blockIdx.x * 128 + t; idx < 384 * 128; idx += 256 * 128) {
        int r = idx >> 7, c = idx & 127;
        g_WgT[c * 384 + r]         = Wih[idx];
        g_WgT[(128 + c) * 384 + r] = Whh[idx];
    }

    for (int s = t; s < 8 * 128; s += 128) {
        float v = input[(size_t)n0 * 128 + s];
        As[s] = v;
        g_m[(size_t)(n0 + (s >> 7)) * MD + (s & 127)] = v;
    }
    __syncthreads();

    float hi[8], hj[8];
#pragma unroll
    for (int r = 0; r < 8; r++) { hi[r] = 0.f; hj[r] = 0.f; }

    for (int e = 0; e < 128; e += 4) {
        float wi0 = preW[(e + 0) * 128 + t];
        float wi1 = preW[(e + 1) * 128 + t];
        float wi2 = preW[(e + 2) * 128 + t];
        float wi3 = preW[(e + 3) * 128 + t];
        float wj0 = preW[(128 + e + 0) * 128 + t];
        float wj1 = preW[(128 + e + 1) * 128 + t];
        float wj2 = preW[(128 + e + 2) * 128 + t];
        float wj3 = preW[(128 + e + 3) * 128 + t];
#pragma unroll
        for (int r = 0; r < 8; r++) {
            const float4 a = *(const float4*)&As[r * 128 + e];
            hi[r] += a.x * wi0 + a.y * wi1 + a.z * wi2 + a.w * wi3;
            hj[r] += a.x * wj0 + a.y * wj1 + a.z * wj2 + a.w * wj3;
        }
    }
#pragma unroll
    for (int r = 0; r < 8; r++) {
        g_hi[(size_t)(n0 + r) * 128 + t] = hi[r];
        g_hj[(size_t)(n0 + r) * 128 + t] = hj[r];
    }
}

// ---------------------------------------------------------------------------
// K2: per-node aggregation.
// ---------------------------------------------------------------------------
#define EST 36

__global__ void __launch_bounds__(128) k2_agg(const float* __restrict__ adj,
                                              const float* __restrict__ adjf,
                                              const float* __restrict__ preW,
                                              const float* __restrict__ preb) {
    __shared__ float WeS[64 * 128];
    __shared__ float efT[64 * EST];
    __shared__ int   nbr[NN];
    __shared__ int   cnt;

    const int t = threadIdx.x;
    const int node = blockIdx.x;
    const int nbase = (node >> 8) << 8;

    {
        const float4* src = (const float4*)(preW + 256 * 128);
        float4* dst = (float4*)WeS;
#pragma unroll
        for (int i = 0; i < 16; i++) dst[t + i * 128] = src[t + i * 128];
    }
    if (t == 0) cnt = 0;
    __syncthreads();

    const float* arow = adj + (size_t)node * NN;
    for (int j = t; j < NN; j += 128)
        if (arow[j] > 0.0f) { int p = atomicAdd(&cnt, 1); nbr[p] = j; }
    __syncthreads();

    const int deg = cnt;
    const float base = g_hi[(size_t)node * 128 + t] + preb[t];
    float s1 = 0.f, s2 = 0.f, mx = -1e30f, mn = 1e30f;
    const float* efb = adjf + (size_t)node * NN * 64;

    for (int p0 = 0; p0 < deg; p0 += 32) {
        __syncthreads();
        {
            const int e = t & 31, kc = (t >> 5) * 16;
            const int j = (p0 + e < deg) ? nbr[p0 + e] : -1;
            if (j >= 0) {
                const float* src = efb + (size_t)j * 64 + kc;
#pragma unroll
                for (int i = 0; i < 16; i += 4) {
                    float4 v = *(const float4*)(src + i);
                    efT[(kc + i + 0) * EST + e] = v.x;
                    efT[(kc + i + 1) * EST + e] = v.y;
                    efT[(kc + i + 2) * EST + e] = v.z;
                    efT[(kc + i + 3) * EST + e] = v.w;
                }
            } else {
#pragma unroll
                for (int i = 0; i < 16; i++) efT[(kc + i) * EST + e] = 0.f;
            }
        }
        __syncthreads();

        float hjv[32];
#pragma unroll
        for (int u = 0; u < 32; u++) {
            int uu = (p0 + u < deg) ? nbr[p0 + u] : nbr[0];
            hjv[u] = g_hj[(size_t)(nbase + uu) * 128 + t];
        }

        ull acc[16];
#pragma unroll
        for (int p = 0; p < 16; p++) acc[p] = 0;

#pragma unroll 4
        for (int de = 0; de < 64; de++) {
            ull w2 = dup(WeS[de * 128 + t]);
            const ull* efr = (const ull*)&efT[de * EST];
#pragma unroll
            for (int q = 0; q < 8; q++) {
                ulonglong2 e2 = *(const ulonglong2*)&efr[q * 2];
                acc[q * 2]     = ffma2(e2.x, w2, acc[q * 2]);
                acc[q * 2 + 1] = ffma2(e2.y, w2, acc[q * 2 + 1]);
            }
        }

#pragma unroll
        for (int p = 0; p < 16; p++) {
            float ea, eb;
            unpk(acc[p], ea, eb);
            int i0 = p0 + 2 * p, i1 = i0 + 1;
            if (i0 < deg) {
                float tv = base + hjv[2 * p] + ea;
                s1 += tv; s2 += tv * tv;
                mx = fmaxf(mx, tv); mn = fminf(mn, tv);
            }
            if (i1 < deg) {
                float tv = base + hjv[2 * p + 1] + eb;
                s1 += tv; s2 += tv * tv;
                mx = fmaxf(mx, tv); mn = fminf(mn, tv);
            }
        }
    }

    float degf = (float)deg;
    float degc = fmaxf(degf, 1e-5f);
    float mean = s1 / degc;
    float var = s2 / degc - mean * mean;
    if (var < 0.f) var = 0.f;
    float sd = sqrtf(var + 1e-5f);
    float mxo = (deg > 0) ? mx : 0.f;
    float mno = (deg > 0) ? mn : 0.f;
    float slog = logf(degf + 1.0f) / 3.3f;
    float inv = 1.0f / (slog + 1e-5f);

    float* mrow = g_m + (size_t)node * MD;
    mrow[ 128 + t] = mean;        mrow[ 256 + t] = mxo;
    mrow[ 384 + t] = mno;         mrow[ 512 + t] = sd;
    mrow[ 640 + t] = mean * slog; mrow[ 768 + t] = mxo * slog;
    mrow[ 896 + t] = mno * slog;  mrow[1024 + t] = sd * slog;
    mrow[1152 + t] = mean * inv;  mrow[1280 + t] = mxo * inv;
    mrow[1408 + t] = mno * inv;   mrow[1536 + t] = sd * inv;
}

// ---------------------------------------------------------------------------
// K3a: post-GEMM partials.
// ---------------------------------------------------------------------------
#define KSP 208
#define AST 68
#define SMEM_K3A (KSP * AST * 4)

__global__ void __launch_bounds__(256, 2) k3a_post(const float* __restrict__ postW) {
    extern __shared__ float AsT[];
    const int tid = threadIdx.x;
    const int w = tid >> 5, lane = tid & 31;
    const int rb = blockIdx.x & 31, ks = blockIdx.x >> 5;
    const int n0 = rb * 64, k0 = ks * KSP;

    {
        const int r = tid >> 2;
        const int kt = (tid & 3) * 52;
        const float* src = g_m + (size_t)(n0 + r) * MD + k0 + kt;
#pragma unroll
        for (int i = 0; i < 52; i += 4) {
            float4 v = *(const float4*)(src + i);
            AsT[(kt + i + 0) * AST + r] = v.x;
            AsT[(kt + i + 1) * AST + r] = v.y;
            AsT[(kt + i + 2) * AST + r] = v.z;
            AsT[(kt + i + 3) * AST + r] = v.w;
        }
    }
    __syncthreads();

    const int rg = lane >> 2;
    const int cp = lane & 3;
    const int c0 = w * 16 + cp * 4;
    const int bs = rg * 8;
    const int sel = (rg >= 4) ? 4 : 0;
    const int offA = bs + sel;
    const int offB = bs + 4 - sel;

    const float* wp = postW + (size_t)k0 * 128 + c0;

    ull aA0[4], aA1[4], aB0[4], aB1[4];
#pragma unroll
    for (int c = 0; c < 4; c++) { aA0[c] = 0; aA1[c] = 0; aB0[c] = 0; aB1[c] = 0; }

#define LOADW3(buf, b)                                                      \
    {                                                                       \
        _Pragma("unroll")                                                   \
        for (int j = 0; j < 4; j++)                                         \
            buf[j] = *(const float4*)(wp + (size_t)((b) * 4 + j) * 128);    \
    }
#define COMP3(b, buf)                                                       \
    {                                                                       \
        _Pragma("unroll")                                                   \
        for (int j = 0; j < 4; j++) {                                       \
            const int k = (b) * 4 + j;                                      \
            ulonglong2 A = *(const ulonglong2*)&AsT[k * AST + offA];        \
            ulonglong2 B = *(const ulonglong2*)&AsT[k * AST + offB];        \
            ull w0 = dup(buf[j].x), w1 = dup(buf[j].y);                     \
            ull w2 = dup(buf[j].z), w3 = dup(buf[j].w);                     \
            aA0[0] = ffma2(A.x, w0, aA0[0]); aA0[1] = ffma2(A.x, w1, aA0[1]); \
            aA0[2] = ffma2(A.x, w2, aA0[2]); aA0[3] = ffma2(A.x, w3, aA0[3]); \
            aA1[0] = ffma2(A.y, w0, aA1[0]); aA1[1] = ffma2(A.y, w1, aA1[1]); \
            aA1[2] = ffma2(A.y, w2, aA1[2]); aA1[3] = ffma2(A.y, w3, aA1[3]); \
            aB0[0] = ffma2(B.x, w0, aB0[0]); aB0[1] = ffma2(B.x, w1, aB0[1]); \
            aB0[2] = ffma2(B.x, w2, aB0[2]); aB0[3] = ffma2(B.x, w3, aB0[3]); \
            aB1[0] = ffma2(B.y, w0, aB1[0]); aB1[1] = ffma2(B.y, w1, aB1[1]); \
            aB1[2] = ffma2(B.y, w2, aB1[2]); aB1[3] = ffma2(B.y, w3, aB1[3]); \
        }                                                                   \
    }

    float4 wA[4], wB[4];
    LOADW3(wA, 0);
    for (int b = 0; b < 52; b += 2) {
        LOADW3(wB, b + 1);
        COMP3(b, wA);
        if (b + 2 < 52) LOADW3(wA, b + 2);
        COMP3(b + 1, wB);
    }
#undef LOADW3
#undef COMP3

    {
        const int rA = n0 + offA;
        const int rB = n0 + offB;
        float lo[4], hi[4];
#pragma unroll
        for (int c = 0; c < 4; c++) unpk(aA0[c], lo[c], hi[c]);
        *(float4*)&g_part[ks][rA][c0]     = make_float4(lo[0], lo[1], lo[2], lo[3]);
        *(float4*)&g_part[ks][rA + 1][c0] = make_float4(hi[0], hi[1], hi[2], hi[3]);
#pragma unroll
        for (int c = 0; c < 4; c++) unpk(aA1[c], lo[c], hi[c]);
        *(float4*)&g_part[ks][rA + 2][c0] = make_float4(lo[0], lo[1], lo[2], lo[3]);
        *(float4*)&g_part[ks][rA + 3][c0] = make_float4(hi[0], hi[1], hi[2], hi[3]);
#pragma unroll
        for (int c = 0; c < 4; c++) unpk(aB0[c], lo[c], hi[c]);
        *(float4*)&g_part[ks][rB][c0]     = make_float4(lo[0], lo[1], lo[2], lo[3]);
        *(float4*)&g_part[ks][rB + 1][c0] = make_float4(hi[0], hi[1], hi[2], hi[3]);
#pragma unroll
        for (int c = 0; c < 4; c++) unpk(aB1[c], lo[c], hi[c]);
        *(float4*)&g_part[ks][rB + 2][c0] = make_float4(lo[0], lo[1], lo[2], lo[3]);
        *(float4*)&g_part[ks][rB + 3][c0] = make_float4(hi[0], hi[1], hi[2], hi[3]);
    }
}

// ---------------------------------------------------------------------------
// K45: fused reduce + mix + GRU gate GEMM (R13 configuration).
// grid 192 = 64 rowblocks(32 rows) x 3 gate-colblocks. 256 threads.
// ---------------------------------------------------------------------------
#define FST 36
#define SMEM_K45 ((128 * FST + 256 * FST) * 4)   // 55296 B

__global__ void __launch_bounds__(256, 2) k45_fused(
        const float* __restrict__ postb,
        const float* __restrict__ mixW, const float* __restrict__ mixb,
        const float* __restrict__ hidden) {
    extern __shared__ float sm[];
    float* YsT = sm;                 // [c][r], c<128
    float* S   = sm + 128 * FST;     // [k][r], k<128 X, k>=128 H

    const int tid = threadIdx.x;
    const int rb = blockIdx.x & 63, cb = blockIdx.x >> 6;
    const int n0 = rb * 32, cg = cb * 128;

    // ---- Phase A: reduce partials -> YsT; hidden -> S[128..255] ----
    {
        const int r = tid >> 3;
        const int c16 = (tid & 7) * 16;
#pragma unroll
        for (int j = 0; j < 4; j++) {
            int c = c16 + j * 4;
            float4 s = *(const float4*)(postb + c);
#pragma unroll
            for (int p = 0; p < 8; p++) {
                float4 v = *(const float4*)&g_part[p][n0 + r][c];
                s.x += v.x; s.y += v.y; s.z += v.z; s.w += v.w;
            }
            YsT[(c + 0) * FST + r] = s.x;
            YsT[(c + 1) * FST + r] = s.y;
            YsT[(c + 2) * FST + r] = s.z;
            YsT[(c + 3) * FST + r] = s.w;
            float4 h = *(const float4*)(hidden + (size_t)(n0 + r) * 128 + c);
            S[(128 + c + 0) * FST + r] = h.x;
            S[(128 + c + 1) * FST + r] = h.y;
            S[(128 + c + 2) * FST + r] = h.z;
            S[(128 + c + 3) * FST + r] = h.w;
        }
    }
    __syncthreads();

    const int w = tid >> 5, lane = tid & 31;
    const int rq = lane >> 2, cp = lane & 3;
    const int c0 = w * 16 + cp * 4;

#define LOADW45(wp, stride, buf, b)                                          \
    {                                                                        \
        _Pragma("unroll")                                                    \
        for (int j = 0; j < 4; j++)                                          \
            buf[j] = *(const float4*)((wp) + (size_t)((b) * 4 + j) * (stride)); \
    }
#define COMP45(base, b, buf)                                                 \
    {                                                                        \
        _Pragma("unroll")                                                    \
        for (int j = 0; j < 4; j++) {                                        \
            const int k = (b) * 4 + j;                                       \
            ulonglong2 A = *(const ulonglong2*)&(base)[k * FST + rq * 4];    \
            ull w0 = dup(buf[j].x), w1 = dup(buf[j].y);                      \
            ull w2 = dup(buf[j].z), w3 = dup(buf[j].w);                      \
            a0[0] = ffma2(A.x, w0, a0[0]); a0[1] = ffma2(A.x, w1, a0[1]);    \
            a0[2] = ffma2(A.x, w2, a0[2]); a0[3] = ffma2(A.x, w3, a0[3]);    \
            a1[0] = ffma2(A.y, w0, a1[0]); a1[1] = ffma2(A.y, w1, a1[1]);    \
            a1[2] = ffma2(A.y, w2, a1[2]); a1[3] = ffma2(A.y, w3, a1[3]);    \
        }                                                                    \
    }

    // ---- Phase B: X = leaky(Y @ mixW + mixb) -> S[0..127] ----
    {
        const float* wp = mixW + c0;
        ull a0[4] = {0, 0, 0, 0}, a1[4] = {0, 0, 0, 0};
        float4 wA[4], wB[4];
        LOADW45(wp, 128, wA, 0);
        for (int b = 0; b < 32; b += 2) {
            LOADW45(wp, 128, wB, b + 1);
            COMP45(YsT, b, wA);
            if (b + 2 < 32) LOADW45(wp, 128, wA, b + 2);
            COMP45(YsT, b + 1, wB);
        }
#pragma unroll
        for (int c = 0; c < 4; c++) {
            float mb = mixb[c0 + c];
            float x0, x1, x2, x3;
            unpk(a0[c], x0, x1);
            unpk(a1[c], x2, x3);
            x0 += mb; x1 += mb; x2 += mb; x3 += mb;
            x0 = (x0 > 0.f) ? x0 : 0.01f * x0;
            x1 = (x1 > 0.f) ? x1 : 0.01f * x1;
            x2 = (x2 > 0.f) ? x2 : 0.01f * x2;
            x3 = (x3 > 0.f) ? x3 : 0.01f * x3;
            *(float4*)&S[(c0 + c) * FST + rq * 4] = make_float4(x0, x1, x2, x3);
        }
    }
    __syncthreads();

    // ---- Phase C: GRU gate GEMM ----
    const int nruns = (cb == 2) ? 2 : 1;
    for (int run = 0; run < nruns; run++) {
        const int kb = (cb == 2) ? run * 128 : 0;
        const int nk = (cb == 2) ? 128 : 256;
        const int wcol = (cb == 2) ? 256 : cg;
        const float* wp = g_WgT + (size_t)kb * 384 + wcol + c0;
        const float* Ab = S + kb * FST;
        const int nb = nk / 4;

        ull a0[4] = {0, 0, 0, 0}, a1[4] = {0, 0, 0, 0};
        float4 wA[4], wB[4];
        LOADW45(wp, 384, wA, 0);
        for (int b = 0; b < nb; b += 2) {
            LOADW45(wp, 384, wB, b + 1);
            COMP45(Ab, b, wA);
            if (b + 2 < nb) LOADW45(wp, 384, wA, b + 2);
            COMP45(Ab, b + 1, wB);
        }

        float* P;
        int st;
        if (cb < 2)        { P = g_gate + cg + c0;  st = 384; }
        else if (run == 0) { P = g_gate + 256 + c0; st = 384; }
        else               { P = g_gateH + c0;      st = 128; }
        const int r0 = n0 + rq * 4;
        float lo[4], hi[4];
#pragma unroll
        for (int c = 0; c < 4; c++) unpk(a0[c], lo[c], hi[c]);
        *(float4*)&P[(size_t)(r0 + 0) * st] = make_float4(lo[0], lo[1], lo[2], lo[3]);
        *(float4*)&P[(size_t)(r0 + 1) * st] = make_float4(hi[0], hi[1], hi[2], hi[3]);
#pragma unroll
        for (int c = 0; c < 4; c++) unpk(a1[c], lo[c], hi[c]);
        *(float4*)&P[(size_t)(r0 + 2) * st] = make_float4(lo[0], lo[1], lo[2], lo[3]);
        *(float4*)&P[(size_t)(r0 + 3) * st] = make_float4(hi[0], hi[1], hi[2], hi[3]);
    }
#undef LOADW45
#undef COMP45
}

// ---------------------------------------------------------------------------
// K6: GRU elementwise epilogue -> out.
// ---------------------------------------------------------------------------
__global__ void __launch_bounds__(256) k6_out(const float* __restrict__ hidden,
                                              float* __restrict__ out) {
    int idx = blockIdx.x * 256 + threadIdx.x;
    int r = idx >> 5;
    int c4 = (idx & 31) * 4;
    const float* g = g_gate + (size_t)r * 384;
    float4 rs = *(const float4*)(g + c4);
    float4 zs = *(const float4*)(g + 128 + c4);
    float4 is = *(const float4*)(g + 256 + c4);
    float4 hn = *(const float4*)&g_gateH[(size_t)r * 128 + c4];
    float4 hv = *(const float4*)(hidden + (size_t)r * 128 + c4);
    float o[4];
    float R[4] = {rs.x, rs.y, rs.z, rs.w};
    float Z[4] = {zs.x, zs.y, zs.z, zs.w};
    float I[4] = {is.x, is.y, is.z, is.w};
    float Hn[4] = {hn.x, hn.y, hn.z, hn.w};
    float Hv[4] = {hv.x, hv.y, hv.z, hv.w};
#pragma unroll
    for (int j = 0; j < 4; j++) {
        float rv = 1.f / (1.f + expf(-R[j]));
        float zv = 1.f / (1.f + expf(-Z[j]));
        float nv = tanhf(I[j] + rv * Hn[j]);
        o[j] = (1.f - zv) * nv + zv * Hv[j];
    }
    *(float4*)&out[(size_t)r * 128 + c4] = make_float4(o[0], o[1], o[2], o[3]);
}

// ---------------------------------------------------------------------------
extern "C" void kernel_launch(void* const* d_in, const int* in_sizes, int n_in,
                              void* d_out, int out_size) {
    const float* input  = (const float*)d_in[0];
    const float* adj    = (const float*)d_in[1];
    const float* adjf   = (const float*)d_in[2];
    const float* hidden = (const float*)d_in[3];
    const float* preW   = (const float*)d_in[4];
    const float* preb   = (const float*)d_in[5];
    const float* postW  = (const float*)d_in[6];
    const float* postb  = (const float*)d_in[7];
    const float* mixW   = (const float*)d_in[8];
    const float* mixb   = (const float*)d_in[9];
    const float* Wih    = (const float*)d_in[10];
    const float* Whh    = (const float*)d_in[11];
    float* out = (float*)d_out;

    cudaFuncSetAttribute(k3a_post, cudaFuncAttributeMaxDynamicSharedMemorySize, SMEM_K3A);
    cudaFuncSetAttribute(k45_fused, cudaFuncAttributeMaxDynamicSharedMemorySize, SMEM_K45);

    k1_hij<<<256, 128>>>(input, preW, Wih, Whh);
    k2_agg<<<BN, 128>>>(adj, adjf, preW, preb);
    k3a_post<<<256, 256, SMEM_K3A>>>(postW);
    k45_fused<<<192, 256, SMEM_K45>>>(postb, mixW, mixb, hidden);
    k6_out<<<256, 256>>>(hidden, out);
}